// round 12
// baseline (speedup 1.0000x reference)
#include <cuda_runtime.h>

// MissHitScatter: out[4, 65536, 1024] f32.
//   out[0]    = inputs (copy, 256 MiB)
//   out[1..3] = 0      (768 MiB zero-fill; d_out poisoned to 0xAA, must write)
//
// Pure HBM streaming: 1.25 GiB traffic. float4 everywhere, 8 float4/thread.
// Each block owns a contiguous 8192-float4 (128 KiB) chunk; region boundary
// (N_IN4) is chunk-aligned, so every block is uniformly copy or zero.

static constexpr long long N_ELEMS = 65536LL * 1024LL;       // input f32 elements
static constexpr long long N_IN4   = N_ELEMS / 4;            // 16,777,216 float4
static constexpr long long N_OUT4  = 4LL * N_ELEMS / 4;      // 67,108,864 float4

static constexpr int  THREADS   = 256;
static constexpr int  V_PER_THR = 8;                          // float4 per thread
static constexpr long long CHUNK = (long long)THREADS * V_PER_THR;  // 8192 float4

__global__ void miss_hit_scatter_kernel(const float4* __restrict__ in4,
                                        float4* __restrict__ out4) {
    const long long base = (long long)blockIdx.x * CHUNK + threadIdx.x;

    if (base < N_IN4) {
        // Copy region — batch all 8 loads up front for MLP=8.
        float4 v[V_PER_THR];
#pragma unroll
        for (int i = 0; i < V_PER_THR; i++)
            v[i] = in4[base + (long long)i * THREADS];
#pragma unroll
        for (int i = 0; i < V_PER_THR; i++)
            out4[base + (long long)i * THREADS] = v[i];
    } else {
        // Zero region — store-only.
        const float4 z = make_float4(0.f, 0.f, 0.f, 0.f);
#pragma unroll
        for (int i = 0; i < V_PER_THR; i++)
            out4[base + (long long)i * THREADS] = z;
    }
}

extern "C" void kernel_launch(void* const* d_in, const int* in_sizes, int n_in,
                              void* d_out, int out_size) {
    const float4* in4 = (const float4*)d_in[0];
    float4* out4 = (float4*)d_out;

    const long long blocks = N_OUT4 / CHUNK;  // 8192 (exact)
    miss_hit_scatter_kernel<<<(unsigned)blocks, THREADS>>>(in4, out4);
}

// round 13
// speedup vs baseline: 1.0145x; 1.0145x over previous
#include <cuda_runtime.h>

// MissHitScatter: out[4, 65536, 1024] f32.
//   out[0]    = inputs (copy, 256 MiB)
//   out[1..3] = 0      (768 MiB zero-fill; d_out poisoned to 0xAA, must write)
//
// Pure HBM streaming: 1.25 GiB traffic. float4 everywhere, 8 float4/thread.
// Each block owns a contiguous 2048-float4 (32 KiB) chunk; region boundary
// (N_IN4 = 8192 chunks) is chunk-aligned, so every block is uniformly copy
// or zero. Grid = 32768 blocks.
//
// R12 baseline: 186.0 us, DRAM 91.1%, HBM 7225 GB/s (90.3% of spec).
// R13 A/B: streaming cache hints (__ldcs/__stcs) — nothing is re-read, so
// skip L2 retention on both streams.

static constexpr long long N_ELEMS = 65536LL * 1024LL;       // input f32 elements
static constexpr long long N_IN4   = N_ELEMS / 4;            // 16,777,216 float4
static constexpr long long N_OUT4  = 4LL * N_ELEMS / 4;      // 67,108,864 float4

static constexpr int  THREADS   = 256;
static constexpr int  V_PER_THR = 8;                          // float4 per thread
static constexpr long long CHUNK = (long long)THREADS * V_PER_THR;  // 2048 float4

__global__ void miss_hit_scatter_kernel(const float4* __restrict__ in4,
                                        float4* __restrict__ out4) {
    const long long base = (long long)blockIdx.x * CHUNK + threadIdx.x;

    if (base < N_IN4) {
        // Copy region — batch all 8 streaming loads up front for MLP=8.
        float4 v[V_PER_THR];
#pragma unroll
        for (int i = 0; i < V_PER_THR; i++)
            v[i] = __ldcs(&in4[base + (long long)i * THREADS]);
#pragma unroll
        for (int i = 0; i < V_PER_THR; i++)
            __stcs(&out4[base + (long long)i * THREADS], v[i]);
    } else {
        // Zero region — store-only, streaming.
        const float4 z = make_float4(0.f, 0.f, 0.f, 0.f);
#pragma unroll
        for (int i = 0; i < V_PER_THR; i++)
            __stcs(&out4[base + (long long)i * THREADS], z);
    }
}

extern "C" void kernel_launch(void* const* d_in, const int* in_sizes, int n_in,
                              void* d_out, int out_size) {
    const float4* in4 = (const float4*)d_in[0];
    float4* out4 = (float4*)d_out;

    const long long blocks = N_OUT4 / CHUNK;  // 32,768 (exact)
    miss_hit_scatter_kernel<<<(unsigned)blocks, THREADS>>>(in4, out4);
}